// round 1
// baseline (speedup 1.0000x reference)
#include <cuda_runtime.h>
#include <math.h>

// ---------------- problem constants ----------------
#define B_SZ  2
#define L_SZ  2048
#define DM    1024
#define DIN   2048
#define NST   16
#define DTR   64
#define M_ROWS (B_SZ * L_SZ)   // 4096
#define XPROJ_N (DTR + 2*NST)  // 96

// ---------------- scratch (static device arrays; no allocation) ----------------
__device__ float g_xn[M_ROWS * DM];           // layernorm output
__device__ float g_xz[M_ROWS * 2 * DIN];      // in_proj output (u | z)
__device__ float g_uc[M_ROWS * DIN];          // silu(conv(u))
__device__ float g_dbc[M_ROWS * XPROJ_N];     // dt | B | C
__device__ float g_delta[M_ROWS * DIN];       // softplus(dt @ dt_proj + b)
__device__ float g_yz[M_ROWS * DIN];          // y * silu(z)

// ---------------- layernorm: one block per row ----------------
__global__ __launch_bounds__(256) void ln_kernel(const float* __restrict__ x,
                                                 const float* __restrict__ g,
                                                 const float* __restrict__ bb) {
    int row = blockIdx.x;
    int t = threadIdx.x;
    const float4* xr = (const float4*)(x + (size_t)row * DM);
    float4 v = xr[t];
    float s  = v.x + v.y + v.z + v.w;
    float sq = v.x*v.x + v.y*v.y + v.z*v.z + v.w*v.w;
    #pragma unroll
    for (int o = 16; o > 0; o >>= 1) {
        s  += __shfl_xor_sync(0xffffffffu, s, o);
        sq += __shfl_xor_sync(0xffffffffu, sq, o);
    }
    __shared__ float rs[8], rq[8];
    int wid = t >> 5, lane = t & 31;
    if (lane == 0) { rs[wid] = s; rq[wid] = sq; }
    __syncthreads();
    float S = 0.f, Q = 0.f;
    #pragma unroll
    for (int i = 0; i < 8; i++) { S += rs[i]; Q += rq[i]; }
    float mean = S * (1.0f / DM);
    float var  = Q * (1.0f / DM) - mean * mean;
    float rstd = rsqrtf(var + 1e-5f);
    float4 gg = ((const float4*)g)[t];
    float4 bv = ((const float4*)bb)[t];
    float4 o;
    o.x = (v.x - mean) * rstd * gg.x + bv.x;
    o.y = (v.y - mean) * rstd * gg.y + bv.y;
    o.z = (v.z - mean) * rstd * gg.z + bv.z;
    o.w = (v.w - mean) * rstd * gg.w + bv.w;
    ((float4*)(g_xn + (size_t)row * DM))[t] = o;
}

// ---------------- generic fp32 tiled GEMM: C = A(MxK) @ W(KxN) ----------------
// EPI: 0 = none, 1 = softplus(acc + bias[n]), 2 = acc + extra[row*lde + n]
template <int EPI>
__global__ __launch_bounds__(256) void gemm_kernel(
    const float* __restrict__ A, int lda,
    const float* __restrict__ W, int ldb,
    float* __restrict__ C, int ldc,
    int M, int N, int K,
    const float* __restrict__ extra, int lde)
{
    const int BM = 64, BN = 64, BK = 16;
    __shared__ __align__(16) float As[BK][BM];
    __shared__ __align__(16) float Bs[BK][BN];

    int tid = threadIdx.x;
    int tx = tid & 15, ty = tid >> 4;
    int m0 = blockIdx.y * BM;
    int n0 = blockIdx.x * BN;

    int a_m = tid >> 2;             // 0..63
    int a_k = (tid & 3) * 4;        // 0,4,8,12
    int b_k = tid >> 4;             // 0..15
    int b_n = (tid & 15) * 4;       // 0..60

    float acc[4][4];
    #pragma unroll
    for (int i = 0; i < 4; i++)
        #pragma unroll
        for (int j = 0; j < 4; j++) acc[i][j] = 0.f;

    for (int k0 = 0; k0 < K; k0 += BK) {
        float4 av = *(const float4*)(A + (size_t)(m0 + a_m) * lda + k0 + a_k);
        As[a_k + 0][a_m] = av.x;
        As[a_k + 1][a_m] = av.y;
        As[a_k + 2][a_m] = av.z;
        As[a_k + 3][a_m] = av.w;
        float4 bv;
        if (n0 + b_n < N)
            bv = *(const float4*)(W + (size_t)(k0 + b_k) * ldb + n0 + b_n);
        else
            bv = make_float4(0.f, 0.f, 0.f, 0.f);
        *(float4*)&Bs[b_k][b_n] = bv;
        __syncthreads();

        #pragma unroll
        for (int k = 0; k < BK; k++) {
            float4 a = *(const float4*)&As[k][ty * 4];
            float4 b = *(const float4*)&Bs[k][tx * 4];
            float ar[4] = {a.x, a.y, a.z, a.w};
            float br[4] = {b.x, b.y, b.z, b.w};
            #pragma unroll
            for (int i = 0; i < 4; i++)
                #pragma unroll
                for (int j = 0; j < 4; j++)
                    acc[i][j] = fmaf(ar[i], br[j], acc[i][j]);
        }
        __syncthreads();
    }

    #pragma unroll
    for (int i = 0; i < 4; i++) {
        int row = m0 + ty * 4 + i;
        #pragma unroll
        for (int j = 0; j < 4; j++) {
            int col = n0 + tx * 4 + j;
            if (col < N) {
                float v = acc[i][j];
                if (EPI == 1) {
                    v += extra[col];
                    v = (v > 20.f) ? v : log1pf(__expf(v));
                } else if (EPI == 2) {
                    v += extra[(size_t)row * lde + col];
                }
                C[(size_t)row * ldc + col] = v;
            }
        }
    }
}

// ---------------- depthwise causal conv (k=4) + SiLU ----------------
__global__ __launch_bounds__(256) void conv_silu_kernel(const float* __restrict__ w,
                                                        const float* __restrict__ cb) {
    int idx = blockIdx.x * blockDim.x + threadIdx.x;
    if (idx >= M_ROWS * DIN) return;
    int d = idx & (DIN - 1);
    int row = idx >> 11;               // /DIN
    int l = row & (L_SZ - 1);
    float acc = cb[d];
    const float* up = g_xz + (size_t)row * (2 * DIN) + d;  // u = first DIN cols
    const float* wd = w + d * 4;
    #pragma unroll
    for (int j = 0; j < 4; j++) {
        int ll = l - 3 + j;
        if (ll >= 0) acc = fmaf(wd[j], up[(j - 3) * (2 * DIN)], acc);
    }
    g_uc[idx] = acc / (1.f + __expf(-acc));   // silu
}

// ---------------- selective scan: 16 lanes per channel, 2 channels per warp ----
__global__ __launch_bounds__(128) void scan_kernel(const float* __restrict__ A_log,
                                                   const float* __restrict__ Dp) {
    int warp = blockIdx.x * (blockDim.x >> 5) + (threadIdx.x >> 5);
    int lane = threadIdx.x & 31;
    int half = lane >> 4;
    int n = lane & 15;
    int ch = warp * 2 + half;          // 0..B*DIN-1
    int b = ch >> 11;                  // /DIN
    int d = ch & (DIN - 1);

    float A  = -__expf(A_log[d * NST + n]);
    float Dd = Dp[d];
    float h = 0.f;

    const float* delta_p = g_delta + (size_t)b * L_SZ * DIN + d;
    const float* u_p     = g_uc    + (size_t)b * L_SZ * DIN + d;
    const float* bc_p    = g_dbc   + (size_t)b * L_SZ * XPROJ_N;
    const float* z_p     = g_xz    + (size_t)b * L_SZ * (2 * DIN) + DIN + d;
    float*       y_p     = g_yz    + (size_t)b * L_SZ * DIN + d;

    #pragma unroll 2
    for (int l = 0; l < L_SZ; l++) {
        float dl = delta_p[(size_t)l * DIN];
        float u  = u_p[(size_t)l * DIN];
        float Bv = bc_p[(size_t)l * XPROJ_N + DTR + n];
        float Cv = bc_p[(size_t)l * XPROJ_N + DTR + NST + n];
        h = fmaf(__expf(dl * A), h, (dl * u) * Bv);
        float p = h * Cv;
        p += __shfl_xor_sync(0xffffffffu, p, 8);
        p += __shfl_xor_sync(0xffffffffu, p, 4);
        p += __shfl_xor_sync(0xffffffffu, p, 2);
        p += __shfl_xor_sync(0xffffffffu, p, 1);
        if (n == 0) {
            float y = p + u * Dd;
            float z = z_p[(size_t)l * (2 * DIN)];
            y_p[(size_t)l * DIN] = y * (z / (1.f + __expf(-z)));
        }
    }
}

// ---------------- launch ----------------
extern "C" void kernel_launch(void* const* d_in, const int* in_sizes, int n_in,
                              void* d_out, int out_size) {
    const float* x         = (const float*)d_in[0];
    const float* in_proj_w = (const float*)d_in[1];
    const float* conv_w    = (const float*)d_in[2];
    const float* conv_b    = (const float*)d_in[3];
    const float* x_proj_w  = (const float*)d_in[4];
    const float* dt_proj_w = (const float*)d_in[5];
    const float* dt_proj_b = (const float*)d_in[6];
    const float* A_log     = (const float*)d_in[7];
    const float* Dp        = (const float*)d_in[8];
    const float* out_proj_w= (const float*)d_in[9];
    const float* ln_g      = (const float*)d_in[10];
    const float* ln_b      = (const float*)d_in[11];
    float* out = (float*)d_out;

    float *p_xn, *p_xz, *p_uc, *p_dbc, *p_delta, *p_yz;
    cudaGetSymbolAddress((void**)&p_xn,    g_xn);
    cudaGetSymbolAddress((void**)&p_xz,    g_xz);
    cudaGetSymbolAddress((void**)&p_uc,    g_uc);
    cudaGetSymbolAddress((void**)&p_dbc,   g_dbc);
    cudaGetSymbolAddress((void**)&p_delta, g_delta);
    cudaGetSymbolAddress((void**)&p_yz,    g_yz);

    // 1. layernorm
    ln_kernel<<<M_ROWS, 256>>>(x, ln_g, ln_b);

    // 2. xz = xn @ in_proj_w  (4096x1024 @ 1024x4096)
    {
        dim3 grid(2 * DIN / 64, M_ROWS / 64);
        gemm_kernel<0><<<grid, 256>>>(p_xn, DM, in_proj_w, 2 * DIN,
                                      p_xz, 2 * DIN, M_ROWS, 2 * DIN, DM,
                                      nullptr, 0);
    }

    // 3. uc = silu(causal depthwise conv(u))
    conv_silu_kernel<<<(M_ROWS * DIN + 255) / 256, 256>>>(conv_w, conv_b);

    // 4. dbc = uc @ x_proj_w  (4096x2048 @ 2048x96)
    {
        dim3 grid((XPROJ_N + 63) / 64, M_ROWS / 64);
        gemm_kernel<0><<<grid, 256>>>(p_uc, DIN, x_proj_w, XPROJ_N,
                                      p_dbc, XPROJ_N, M_ROWS, XPROJ_N, DIN,
                                      nullptr, 0);
    }

    // 5. delta = softplus(dt @ dt_proj_w + dt_proj_b)  (4096x64 @ 64x2048)
    {
        dim3 grid(DIN / 64, M_ROWS / 64);
        gemm_kernel<1><<<grid, 256>>>(p_dbc, XPROJ_N, dt_proj_w, DIN,
                                      p_delta, DIN, M_ROWS, DIN, DTR,
                                      dt_proj_b, 0);
    }

    // 6. selective scan + gate:  yz = scan(...) * silu(z)
    scan_kernel<<<(B_SZ * DIN / 2) / 4, 128>>>(A_log, Dp);

    // 7. out = yz @ out_proj_w + x  (4096x2048 @ 2048x1024)
    {
        dim3 grid(DM / 64, M_ROWS / 64);
        gemm_kernel<2><<<grid, 256>>>(p_yz, DIN, out_proj_w, DM,
                                      out, DM, M_ROWS, DM, DIN,
                                      x, DM);
    }
}

// round 3
// speedup vs baseline: 1.0794x; 1.0794x over previous
#include <cuda_runtime.h>
#include <math.h>

// ============ HybridBlock R3 (resubmit of R2 after infra failure) ============

// ---------------- problem constants ----------------
#define B_SZ  2
#define L_SZ  2048
#define DM    1024
#define DIN   2048
#define NST   16
#define DTR   64
#define M_ROWS (B_SZ * L_SZ)   // 4096
#define XPROJ_N (DTR + 2*NST)  // 96

// ---------------- scratch ----------------
__device__ float g_xn[M_ROWS * DM];
__device__ float g_xz[M_ROWS * 2 * DIN];
__device__ float g_uc[M_ROWS * DIN];
__device__ float g_dbc[M_ROWS * XPROJ_N];
__device__ float g_delta[M_ROWS * DIN];
__device__ float g_yz[M_ROWS * DIN];

// ---------------- packed f32x2 helpers ----------------
#define PACK2(d, lo, hi) \
    asm("mov.b64 %0, {%1, %2};" : "=l"(d) : "r"(__float_as_uint(lo)), "r"(__float_as_uint(hi)))
#define UNPACK2(lo, hi, s) do { unsigned _ulo, _uhi; \
    asm("mov.b64 {%0, %1}, %2;" : "=r"(_ulo), "=r"(_uhi) : "l"(s)); \
    lo = __uint_as_float(_ulo); hi = __uint_as_float(_uhi); } while (0)
#define FMA2(d, a, b, c) \
    asm("fma.rn.f32x2 %0, %1, %2, %3;" : "=l"(d) : "l"(a), "l"(b), "l"(c))

// ---------------- layernorm ----------------
__global__ __launch_bounds__(256) void ln_kernel(const float* __restrict__ x,
                                                 const float* __restrict__ g,
                                                 const float* __restrict__ bb) {
    int row = blockIdx.x;
    int t = threadIdx.x;
    const float4* xr = (const float4*)(x + (size_t)row * DM);
    float4 v = xr[t];
    float s  = v.x + v.y + v.z + v.w;
    float sq = v.x*v.x + v.y*v.y + v.z*v.z + v.w*v.w;
    #pragma unroll
    for (int o = 16; o > 0; o >>= 1) {
        s  += __shfl_xor_sync(0xffffffffu, s, o);
        sq += __shfl_xor_sync(0xffffffffu, sq, o);
    }
    __shared__ float rs[8], rq[8];
    int wid = t >> 5, lane = t & 31;
    if (lane == 0) { rs[wid] = s; rq[wid] = sq; }
    __syncthreads();
    float S = 0.f, Q = 0.f;
    #pragma unroll
    for (int i = 0; i < 8; i++) { S += rs[i]; Q += rq[i]; }
    float mean = S * (1.0f / DM);
    float var  = Q * (1.0f / DM) - mean * mean;
    float rstd = rsqrtf(var + 1e-5f);
    float4 gg = ((const float4*)g)[t];
    float4 bv = ((const float4*)bb)[t];
    float4 o;
    o.x = (v.x - mean) * rstd * gg.x + bv.x;
    o.y = (v.y - mean) * rstd * gg.y + bv.y;
    o.z = (v.z - mean) * rstd * gg.z + bv.z;
    o.w = (v.w - mean) * rstd * gg.w + bv.w;
    ((float4*)(g_xn + (size_t)row * DM))[t] = o;
}

// ---------------- 128x128x16 double-buffered FFMA2 GEMM ----------------
// C = A(MxK) @ W(KxN).  EPI: 0 none, 1 softplus(+bias[n]), 2 +extra[row,n]
// Requires M%128==0, N%128==0, K%16==0.
template <int EPI>
__global__ __launch_bounds__(256) void gemm128(
    const float* __restrict__ A, int lda,
    const float* __restrict__ W, int ldb,
    float* __restrict__ C, int ldc,
    int K,
    const float* __restrict__ extra, int lde)
{
    const int BM = 128, BN = 128, BK = 16;
    __shared__ __align__(16) float As[2][BK][BM];
    __shared__ __align__(16) float Bs[2][BK][BN];

    int tid = threadIdx.x;
    int m0 = blockIdx.y * BM;
    int n0 = blockIdx.x * BN;

    // 8 warps as 4(m) x 2(n); within warp 4(m) x 8(n) threads
    int warp = tid >> 5, lane = tid & 31;
    int tm = (warp & 3) * 32 + (lane >> 3) * 8;
    int tn = (warp >> 2) * 64 + (lane & 7) * 8;

    unsigned long long acc2[8][4];
    #pragma unroll
    for (int i = 0; i < 8; i++)
        #pragma unroll
        for (int j = 0; j < 4; j++) acc2[i][j] = 0ull;

    // ---- preload tile 0 ----
    #pragma unroll
    for (int i = 0; i < 2; i++) {
        int idx = tid + 256 * i;
        int am = idx >> 2, kq = (idx & 3) * 4;
        float4 v = *(const float4*)(A + (size_t)(m0 + am) * lda + kq);
        As[0][kq + 0][am] = v.x; As[0][kq + 1][am] = v.y;
        As[0][kq + 2][am] = v.z; As[0][kq + 3][am] = v.w;
        int bk = idx >> 5, bn = (idx & 31) * 4;
        *(float4*)&Bs[0][bk][bn] = *(const float4*)(W + (size_t)bk * ldb + n0 + bn);
    }
    __syncthreads();

    int nIter = K / BK;
    float4 pa[2], pb[2];
    for (int it = 0; it < nIter; it++) {
        int cur = it & 1;
        if (it + 1 < nIter) {
            int k0 = (it + 1) * BK;
            #pragma unroll
            for (int i = 0; i < 2; i++) {
                int idx = tid + 256 * i;
                int am = idx >> 2, kq = (idx & 3) * 4;
                pa[i] = *(const float4*)(A + (size_t)(m0 + am) * lda + k0 + kq);
                int bk = idx >> 5, bn = (idx & 31) * 4;
                pb[i] = *(const float4*)(W + (size_t)(k0 + bk) * ldb + n0 + bn);
            }
        }
        #pragma unroll
        for (int k = 0; k < BK; k++) {
            float4 a0 = *(const float4*)&As[cur][k][tm];
            float4 a1 = *(const float4*)&As[cur][k][tm + 4];
            float4 b0 = *(const float4*)&Bs[cur][k][tn];
            float4 b1 = *(const float4*)&Bs[cur][k][tn + 4];
            float ar[8] = {a0.x, a0.y, a0.z, a0.w, a1.x, a1.y, a1.z, a1.w};
            float br[8] = {b0.x, b0.y, b0.z, b0.w, b1.x, b1.y, b1.z, b1.w};
            unsigned long long bp[4];
            #pragma unroll
            for (int j = 0; j < 4; j++) PACK2(bp[j], br[2*j], br[2*j+1]);
            #pragma unroll
            for (int i = 0; i < 8; i++) {
                unsigned long long ad;
                PACK2(ad, ar[i], ar[i]);
                #pragma unroll
                for (int j = 0; j < 4; j++)
                    FMA2(acc2[i][j], ad, bp[j], acc2[i][j]);
            }
        }
        if (it + 1 < nIter) {
            int nxt = cur ^ 1;
            #pragma unroll
            for (int i = 0; i < 2; i++) {
                int idx = tid + 256 * i;
                int am = idx >> 2, kq = (idx & 3) * 4;
                As[nxt][kq + 0][am] = pa[i].x; As[nxt][kq + 1][am] = pa[i].y;
                As[nxt][kq + 2][am] = pa[i].z; As[nxt][kq + 3][am] = pa[i].w;
                int bk = idx >> 5, bn = (idx & 31) * 4;
                *(float4*)&Bs[nxt][bk][bn] = pb[i];
            }
        }
        __syncthreads();
    }

    // ---- epilogue ----
    #pragma unroll
    for (int i = 0; i < 8; i++) {
        int row = m0 + tm + i;
        float c[8];
        #pragma unroll
        for (int j = 0; j < 4; j++) UNPACK2(c[2*j], c[2*j+1], acc2[i][j]);
        #pragma unroll
        for (int j = 0; j < 8; j++) {
            int col = n0 + tn + j;
            if (EPI == 1) {
                float v = c[j] + extra[col];
                c[j] = (v > 20.f) ? v : log1pf(__expf(v));
            } else if (EPI == 2) {
                c[j] += extra[(size_t)row * lde + col];
            }
        }
        *(float4*)(C + (size_t)row * ldc + n0 + tn)     = *(float4*)&c[0];
        *(float4*)(C + (size_t)row * ldc + n0 + tn + 4) = *(float4*)&c[4];
    }
}

// ---------------- zero kernel (for split-K accumulation buffer) ----------------
__global__ __launch_bounds__(256) void zero_kernel(float* p, int n4) {
    int i = blockIdx.x * blockDim.x + threadIdx.x;
    if (i < n4) ((float4*)p)[i] = make_float4(0.f, 0.f, 0.f, 0.f);
}

// ---------------- 64x64 split-K GEMM with atomic epilogue (x_proj) ----------------
__global__ __launch_bounds__(256) void gemm64_splitk(
    const float* __restrict__ A, int lda,
    const float* __restrict__ W, int ldb,
    float* __restrict__ C, int ldc,
    int N, int KS)
{
    const int BM = 64, BN = 64, BK = 16;
    __shared__ __align__(16) float As[BK][BM];
    __shared__ __align__(16) float Bs[BK][BN];

    int tid = threadIdx.x;
    int tx = tid & 15, ty = tid >> 4;
    int m0 = blockIdx.y * BM;
    int n0 = blockIdx.x * BN;
    int koff = blockIdx.z * KS;

    int a_m = tid >> 2;
    int a_k = (tid & 3) * 4;
    int b_k = tid >> 4;
    int b_n = (tid & 15) * 4;

    float acc[4][4];
    #pragma unroll
    for (int i = 0; i < 4; i++)
        #pragma unroll
        for (int j = 0; j < 4; j++) acc[i][j] = 0.f;

    for (int k0 = koff; k0 < koff + KS; k0 += BK) {
        float4 av = *(const float4*)(A + (size_t)(m0 + a_m) * lda + k0 + a_k);
        As[a_k + 0][a_m] = av.x;
        As[a_k + 1][a_m] = av.y;
        As[a_k + 2][a_m] = av.z;
        As[a_k + 3][a_m] = av.w;
        float4 bv = make_float4(0.f, 0.f, 0.f, 0.f);
        if (n0 + b_n < N)
            bv = *(const float4*)(W + (size_t)(k0 + b_k) * ldb + n0 + b_n);
        *(float4*)&Bs[b_k][b_n] = bv;
        __syncthreads();

        #pragma unroll
        for (int k = 0; k < BK; k++) {
            float4 a = *(const float4*)&As[k][ty * 4];
            float4 b = *(const float4*)&Bs[k][tx * 4];
            float ar[4] = {a.x, a.y, a.z, a.w};
            float br[4] = {b.x, b.y, b.z, b.w};
            #pragma unroll
            for (int i = 0; i < 4; i++)
                #pragma unroll
                for (int j = 0; j < 4; j++)
                    acc[i][j] = fmaf(ar[i], br[j], acc[i][j]);
        }
        __syncthreads();
    }

    #pragma unroll
    for (int i = 0; i < 4; i++) {
        int row = m0 + ty * 4 + i;
        #pragma unroll
        for (int j = 0; j < 4; j++) {
            int col = n0 + tx * 4 + j;
            if (col < N)
                atomicAdd(C + (size_t)row * ldc + col, acc[i][j]);
        }
    }
}

// ---------------- depthwise causal conv (k=4) + SiLU ----------------
__global__ __launch_bounds__(256) void conv_silu_kernel(const float* __restrict__ w,
                                                        const float* __restrict__ cb) {
    int idx = blockIdx.x * blockDim.x + threadIdx.x;
    if (idx >= M_ROWS * DIN) return;
    int d = idx & (DIN - 1);
    int row = idx >> 11;
    int l = row & (L_SZ - 1);
    float acc = cb[d];
    const float* up = g_xz + (size_t)row * (2 * DIN) + d;
    const float* wd = w + d * 4;
    #pragma unroll
    for (int j = 0; j < 4; j++) {
        int ll = l - 3 + j;
        if (ll >= 0) acc = fmaf(wd[j], up[(j - 3) * (2 * DIN)], acc);
    }
    g_uc[idx] = acc / (1.f + __expf(-acc));
}

// ---------------- selective scan ----------------
__global__ __launch_bounds__(128) void scan_kernel(const float* __restrict__ A_log,
                                                   const float* __restrict__ Dp) {
    int warp = blockIdx.x * (blockDim.x >> 5) + (threadIdx.x >> 5);
    int lane = threadIdx.x & 31;
    int half = lane >> 4;
    int n = lane & 15;
    int ch = warp * 2 + half;
    int b = ch >> 11;
    int d = ch & (DIN - 1);

    float A  = -__expf(A_log[d * NST + n]);
    float Dd = Dp[d];
    float h = 0.f;

    const float* delta_p = g_delta + (size_t)b * L_SZ * DIN + d;
    const float* u_p     = g_uc    + (size_t)b * L_SZ * DIN + d;
    const float* bc_p    = g_dbc   + (size_t)b * L_SZ * XPROJ_N;
    const float* z_p     = g_xz    + (size_t)b * L_SZ * (2 * DIN) + DIN + d;
    float*       y_p     = g_yz    + (size_t)b * L_SZ * DIN + d;

    #pragma unroll 2
    for (int l = 0; l < L_SZ; l++) {
        float dl = delta_p[(size_t)l * DIN];
        float u  = u_p[(size_t)l * DIN];
        float Bv = bc_p[(size_t)l * XPROJ_N + DTR + n];
        float Cv = bc_p[(size_t)l * XPROJ_N + DTR + NST + n];
        h = fmaf(__expf(dl * A), h, (dl * u) * Bv);
        float p = h * Cv;
        p += __shfl_xor_sync(0xffffffffu, p, 8);
        p += __shfl_xor_sync(0xffffffffu, p, 4);
        p += __shfl_xor_sync(0xffffffffu, p, 2);
        p += __shfl_xor_sync(0xffffffffu, p, 1);
        if (n == 0) {
            float y = p + u * Dd;
            float z = z_p[(size_t)l * (2 * DIN)];
            y_p[(size_t)l * DIN] = y * (z / (1.f + __expf(-z)));
        }
    }
}

// ---------------- launch ----------------
extern "C" void kernel_launch(void* const* d_in, const int* in_sizes, int n_in,
                              void* d_out, int out_size) {
    const float* x         = (const float*)d_in[0];
    const float* in_proj_w = (const float*)d_in[1];
    const float* conv_w    = (const float*)d_in[2];
    const float* conv_b    = (const float*)d_in[3];
    const float* x_proj_w  = (const float*)d_in[4];
    const float* dt_proj_w = (const float*)d_in[5];
    const float* dt_proj_b = (const float*)d_in[6];
    const float* A_log     = (const float*)d_in[7];
    const float* Dp        = (const float*)d_in[8];
    const float* out_proj_w= (const float*)d_in[9];
    const float* ln_g      = (const float*)d_in[10];
    const float* ln_b      = (const float*)d_in[11];
    float* out = (float*)d_out;

    float *p_xn, *p_xz, *p_uc, *p_dbc, *p_delta, *p_yz;
    cudaGetSymbolAddress((void**)&p_xn,    g_xn);
    cudaGetSymbolAddress((void**)&p_xz,    g_xz);
    cudaGetSymbolAddress((void**)&p_uc,    g_uc);
    cudaGetSymbolAddress((void**)&p_dbc,   g_dbc);
    cudaGetSymbolAddress((void**)&p_delta, g_delta);
    cudaGetSymbolAddress((void**)&p_yz,    g_yz);

    // 0. zero dbc (split-K accumulation target)
    zero_kernel<<<(M_ROWS * XPROJ_N / 4 + 255) / 256, 256>>>(p_dbc, M_ROWS * XPROJ_N / 4);

    // 1. layernorm
    ln_kernel<<<M_ROWS, 256>>>(x, ln_g, ln_b);

    // 2. xz = xn @ in_proj_w  (4096x1024 @ 1024x4096)
    {
        dim3 grid(2 * DIN / 128, M_ROWS / 128);
        gemm128<0><<<grid, 256>>>(p_xn, DM, in_proj_w, 2 * DIN,
                                  p_xz, 2 * DIN, DM, nullptr, 0);
    }

    // 3. uc = silu(causal depthwise conv(u))
    conv_silu_kernel<<<(M_ROWS * DIN + 255) / 256, 256>>>(conv_w, conv_b);

    // 4. dbc += uc @ x_proj_w  (split-K: 8 chunks of 256)
    {
        dim3 grid((XPROJ_N + 63) / 64, M_ROWS / 64, 8);
        gemm64_splitk<<<grid, 256>>>(p_uc, DIN, x_proj_w, XPROJ_N,
                                     p_dbc, XPROJ_N, XPROJ_N, DIN / 8);
    }

    // 5. delta = softplus(dt @ dt_proj_w + dt_proj_b)  (4096x64 @ 64x2048)
    {
        dim3 grid(DIN / 128, M_ROWS / 128);
        gemm128<1><<<grid, 256>>>(p_dbc, XPROJ_N, dt_proj_w, DIN,
                                  p_delta, DIN, DTR, dt_proj_b, 0);
    }

    // 6. selective scan + gate
    scan_kernel<<<(B_SZ * DIN / 2) / 4, 128>>>(A_log, Dp);

    // 7. out = yz @ out_proj_w + x  (4096x2048 @ 2048x1024)
    {
        dim3 grid(DM / 128, M_ROWS / 128);
        gemm128<2><<<grid, 256>>>(p_yz, DIN, out_proj_w, DM,
                                  out, DM, DIN, x, DM);
    }
}

// round 6
// speedup vs baseline: 1.4060x; 1.3026x over previous
#include <cuda_runtime.h>
#include <cuda_bf16.h>
#include <math.h>
#include <stdint.h>

// ---------------- problem constants ----------------
#define B_SZ  2
#define L_SZ  2048
#define DM    1024
#define DIN   2048
#define NST   16
#define DTR   64
#define M_ROWS (B_SZ * L_SZ)   // 4096
#define XPROJ_N (DTR + 2*NST)  // 96

// ---------------- scratch ----------------
__device__ __align__(256) float g_xz[M_ROWS * 2 * DIN];
__device__ __align__(256) float g_uc[M_ROWS * DIN];
__device__ __align__(256) float g_dbc[M_ROWS * XPROJ_N];
__device__ __align__(256) float g_delta[M_ROWS * DIN];
__device__ __align__(256) float g_yz[M_ROWS * DIN];

// split-bf16 expanded operands
__device__ __align__(256) __nv_bfloat16 gA1 [M_ROWS * 3 * DM];
__device__ __align__(256) __nv_bfloat16 gB1 [(2*DIN) * 3 * DM];
__device__ __align__(256) __nv_bfloat16 gAdt[M_ROWS * 3 * DTR];
__device__ __align__(256) __nv_bfloat16 gBdt[DIN * 3 * DTR];
__device__ __align__(256) __nv_bfloat16 gAy [M_ROWS * 3 * DIN];
__device__ __align__(256) __nv_bfloat16 gBo [DM * 3 * DIN];

// ---------------- PTX helpers (all baseline sm_80/75 features) ----------------
__device__ __forceinline__ uint32_t smem_u32(const void* p) {
    uint32_t a;
    asm("{ .reg .u64 t; cvta.to.shared.u64 t, %1; cvt.u32.u64 %0, t; }" : "=r"(a) : "l"(p));
    return a;
}
#define CP_ASYNC16(dst, src) \
    asm volatile("cp.async.cg.shared.global [%0], [%1], 16;" :: "r"(dst), "l"(src) : "memory")
#define CP_COMMIT() asm volatile("cp.async.commit_group;" ::: "memory")
#define CP_WAIT(n)  asm volatile("cp.async.wait_group %0;" :: "n"(n) : "memory")
#define LDSM_X4(r, a) \
    asm volatile("ldmatrix.sync.aligned.m8n8.x4.shared.b16 {%0,%1,%2,%3}, [%4];" \
        : "=r"((r)[0]), "=r"((r)[1]), "=r"((r)[2]), "=r"((r)[3]) : "r"(a))
#define MMA16816(c, a, b0, b1) \
    asm volatile("mma.sync.aligned.m16n8k16.row.col.f32.bf16.bf16.f32 " \
        "{%0,%1,%2,%3}, {%4,%5,%6,%7}, {%8,%9}, {%0,%1,%2,%3};" \
        : "+f"((c)[0]), "+f"((c)[1]), "+f"((c)[2]), "+f"((c)[3]) \
        : "r"((a)[0]), "r"((a)[1]), "r"((a)[2]), "r"((a)[3]), "r"(b0), "r"(b1))

// ---------------- ln + expand:  x -> [hi|hi|lo] bf16 ----------------
__global__ __launch_bounds__(256) void ln_expand(const float* __restrict__ x,
                                                 const float* __restrict__ g,
                                                 const float* __restrict__ bb) {
    int row = blockIdx.x;
    int t = threadIdx.x;
    float4 v = ((const float4*)(x + (size_t)row * DM))[t];
    float s  = v.x + v.y + v.z + v.w;
    float sq = v.x*v.x + v.y*v.y + v.z*v.z + v.w*v.w;
    #pragma unroll
    for (int o = 16; o > 0; o >>= 1) {
        s  += __shfl_xor_sync(0xffffffffu, s, o);
        sq += __shfl_xor_sync(0xffffffffu, sq, o);
    }
    __shared__ float rs[8], rq[8];
    int wid = t >> 5, lane = t & 31;
    if (lane == 0) { rs[wid] = s; rq[wid] = sq; }
    __syncthreads();
    float S = 0.f, Q = 0.f;
    #pragma unroll
    for (int i = 0; i < 8; i++) { S += rs[i]; Q += rq[i]; }
    float mean = S * (1.0f / DM);
    float var  = Q * (1.0f / DM) - mean * mean;
    float rstd = rsqrtf(var + 1e-5f);
    float4 gg = ((const float4*)g)[t];
    float4 bv = ((const float4*)bb)[t];
    float o[4];
    o[0] = (v.x - mean) * rstd * gg.x + bv.x;
    o[1] = (v.y - mean) * rstd * gg.y + bv.y;
    o[2] = (v.z - mean) * rstd * gg.z + bv.z;
    o[3] = (v.w - mean) * rstd * gg.w + bv.w;
    __nv_bfloat16 hi[4], lo[4];
    #pragma unroll
    for (int i = 0; i < 4; i++) {
        hi[i] = __float2bfloat16(o[i]);
        lo[i] = __float2bfloat16(o[i] - __bfloat162float(hi[i]));
    }
    size_t base = (size_t)row * (3 * DM);
    int k = t * 4;
    *(uint64_t*)(gA1 + base + k)          = *(uint64_t*)hi;
    *(uint64_t*)(gA1 + base + DM + k)     = *(uint64_t*)hi;
    *(uint64_t*)(gA1 + base + 2 * DM + k) = *(uint64_t*)lo;
}

// ---------------- generic A expand: A[M,K] (stride ldin) -> [hi|hi|lo] ----------------
__global__ __launch_bounds__(256) void aexp(const float* __restrict__ A, int ldin,
                                            __nv_bfloat16* __restrict__ Ap, int K, int M) {
    int kq = K >> 2;
    int idx = blockIdx.x * blockDim.x + threadIdx.x;
    if (idx >= M * kq) return;
    int m = idx / kq, k = (idx - m * kq) * 4;
    float4 v = *(const float4*)(A + (size_t)m * ldin + k);
    float o[4] = {v.x, v.y, v.z, v.w};
    __nv_bfloat16 hi[4], lo[4];
    #pragma unroll
    for (int i = 0; i < 4; i++) {
        hi[i] = __float2bfloat16(o[i]);
        lo[i] = __float2bfloat16(o[i] - __bfloat162float(hi[i]));
    }
    size_t base = (size_t)m * (3 * K);
    *(uint64_t*)(Ap + base + k)         = *(uint64_t*)hi;
    *(uint64_t*)(Ap + base + K + k)     = *(uint64_t*)hi;
    *(uint64_t*)(Ap + base + 2 * K + k) = *(uint64_t*)lo;
}

// ---------------- weight transpose+expand: W[K,N] -> Bp[N,3K] = [hi|lo|hi] ----------------
__global__ __launch_bounds__(256) void wexpT(const float* __restrict__ W,
                                             __nv_bfloat16* __restrict__ Bp, int K, int N) {
    __shared__ float tile[32][33];
    int k0 = blockIdx.y * 32, n0 = blockIdx.x * 32;
    int tx = threadIdx.x & 31, ty = threadIdx.x >> 5;
    #pragma unroll
    for (int i = 0; i < 32; i += 8)
        tile[ty + i][tx] = W[(size_t)(k0 + ty + i) * N + n0 + tx];
    __syncthreads();
    #pragma unroll
    for (int i = 0; i < 32; i += 8) {
        int n = n0 + ty + i;
        int k = k0 + tx;
        float v = tile[tx][ty + i];
        __nv_bfloat16 hi = __float2bfloat16(v);
        __nv_bfloat16 lo = __float2bfloat16(v - __bfloat162float(hi));
        size_t base = (size_t)n * (3 * K);
        Bp[base + k]         = hi;
        Bp[base + K + k]     = lo;
        Bp[base + 2 * K + k] = hi;
    }
}

// ---------------- mma.sync bf16 GEMM: C[M,N] = A'[M,K3] @ B'[N,K3]^T ----------------
// Block 128x128, BK=32, 8 warps (4m x 2n), warp tile 32x64.
// EPI: 0 plain, 1 softplus(+bias[col]), 2 +extra[row,col]
template <int EPI>
__global__ __launch_bounds__(256, 2) void gemm_mma(
    const __nv_bfloat16* __restrict__ Ag,
    const __nv_bfloat16* __restrict__ Bg,
    int K3, float* __restrict__ C, int ldc,
    const float* __restrict__ extra, int lde)
{
    __shared__ __align__(1024) char smA[2][8192];
    __shared__ __align__(1024) char smB[2][8192];

    int tid = threadIdx.x, lane = tid & 31, wid = tid >> 5;
    int m0 = blockIdx.y * 128, n0 = blockIdx.x * 128;
    int wm = (wid & 3) * 32, wn = (wid >> 2) * 64;

    float c[2][8][4];
    #pragma unroll
    for (int t = 0; t < 2; t++)
        #pragma unroll
        for (int j = 0; j < 8; j++)
            #pragma unroll
            for (int q = 0; q < 4; q++) c[t][j][q] = 0.f;

    const __nv_bfloat16* Arow = Ag + (size_t)m0 * K3;
    const __nv_bfloat16* Brow = Bg + (size_t)n0 * K3;

    // copy mapping: 512 chunks of 16B per tile; thread handles chunks tid, tid+256
    int r0 = tid >> 2,        g0 = tid & 3;
    int r1 = (tid + 256) >> 2, g1 = tid & 3;  // (tid+256)&3 == tid&3
    uint32_t oA0 = (uint32_t)(r0 * 64 + ((g0 * 16) ^ ((r0 & 6) << 3)));
    uint32_t oA1 = (uint32_t)(r1 * 64 + ((g1 * 16) ^ ((r1 & 6) << 3)));
    uint32_t sA[2] = { smem_u32(&smA[0][0]), smem_u32(&smA[1][0]) };
    uint32_t sB[2] = { smem_u32(&smB[0][0]), smem_u32(&smB[1][0]) };

    auto issue = [&](int buf, int kt) {
        CP_ASYNC16(sA[buf] + oA0, Arow + (size_t)r0 * K3 + kt + g0 * 8);
        CP_ASYNC16(sA[buf] + oA1, Arow + (size_t)r1 * K3 + kt + g1 * 8);
        CP_ASYNC16(sB[buf] + oA0, Brow + (size_t)r0 * K3 + kt + g0 * 8);
        CP_ASYNC16(sB[buf] + oA1, Brow + (size_t)r1 * K3 + kt + g1 * 8);
        CP_COMMIT();
    };

    // ldmatrix per-lane geometry
    int arow = lane & 15;                       // row within m16 tile
    uint32_t akx = (lane & 16) ? 16u : 0u;      // +8 cols (16B)
    int brow = (lane & 7) + ((lane & 16) ? 8 : 0);
    uint32_t bkx = (lane & 8) ? 16u : 0u;

    int nIter = K3 / 32;
    issue(0, 0);

    for (int it = 0; it < nIter; it++) {
        int cur = it & 1;
        if (it + 1 < nIter) { issue(cur ^ 1, (it + 1) * 32); CP_WAIT(1); }
        else                { CP_WAIT(0); }
        __syncthreads();

        #pragma unroll
        for (int ks = 0; ks < 2; ks++) {
            uint32_t af[2][4];
            #pragma unroll
            for (int t = 0; t < 2; t++) {
                int row = wm + 16 * t + arow;
                uint32_t addr = sA[cur] + row * 64 + (((uint32_t)ks * 32 + akx) ^ ((row & 6) << 3));
                LDSM_X4(af[t], addr);
            }
            uint32_t bf[4][4];
            #pragma unroll
            for (int p = 0; p < 4; p++) {
                int row = wn + 16 * p + brow;
                uint32_t addr = sB[cur] + row * 64 + (((uint32_t)ks * 32 + bkx) ^ ((row & 6) << 3));
                LDSM_X4(bf[p], addr);
            }
            #pragma unroll
            for (int t = 0; t < 2; t++)
                #pragma unroll
                for (int j = 0; j < 8; j++)
                    MMA16816(c[t][j], af[t], bf[j >> 1][2 * (j & 1)], bf[j >> 1][2 * (j & 1) + 1]);
        }
        __syncthreads();
    }

    // ---- epilogue: direct fragment stores (float2) ----
    int rbase = m0 + wm + (lane >> 2);
    int cbase = n0 + wn + (lane & 3) * 2;
    #pragma unroll
    for (int t = 0; t < 2; t++) {
        #pragma unroll
        for (int j = 0; j < 8; j++) {
            int col = cbase + 8 * j;
            #pragma unroll
            for (int h = 0; h < 2; h++) {       // h=0: rows, h=1: rows+8
                int row = rbase + 16 * t + 8 * h;
                float v0 = c[t][j][2 * h], v1 = c[t][j][2 * h + 1];
                if (EPI == 1) {
                    float t0 = v0 + extra[col],     t1 = v1 + extra[col + 1];
                    v0 = (t0 > 20.f) ? t0 : log1pf(__expf(t0));
                    v1 = (t1 > 20.f) ? t1 : log1pf(__expf(t1));
                } else if (EPI == 2) {
                    v0 += extra[(size_t)row * lde + col];
                    v1 += extra[(size_t)row * lde + col + 1];
                }
                float2 st = make_float2(v0, v1);
                *(float2*)(C + (size_t)row * ldc + col) = st;
            }
        }
    }
}

// ---------------- zero kernel ----------------
__global__ __launch_bounds__(256) void zero_kernel(float* p, int n4) {
    int i = blockIdx.x * blockDim.x + threadIdx.x;
    if (i < n4) ((float4*)p)[i] = make_float4(0.f, 0.f, 0.f, 0.f);
}

// ---------------- x_proj: 64x64 split-K fp32 GEMM, atomic epilogue ----------------
__global__ __launch_bounds__(256) void gemm64_splitk(
    const float* __restrict__ A, int lda,
    const float* __restrict__ W, int ldb,
    float* __restrict__ C, int ldc,
    int N, int KS)
{
    const int BK = 16;
    __shared__ __align__(16) float As[BK][64];
    __shared__ __align__(16) float Bs[BK][64];

    int tid = threadIdx.x;
    int tx = tid & 15, ty = tid >> 4;
    int m0 = blockIdx.y * 64;
    int n0 = blockIdx.x * 64;
    int koff = blockIdx.z * KS;

    int a_m = tid >> 2;
    int a_k = (tid & 3) * 4;
    int b_k = tid >> 4;
    int b_n = (tid & 15) * 4;

    float acc[4][4];
    #pragma unroll
    for (int i = 0; i < 4; i++)
        #pragma unroll
        for (int j = 0; j < 4; j++) acc[i][j] = 0.f;

    for (int k0 = koff; k0 < koff + KS; k0 += BK) {
        float4 av = *(const float4*)(A + (size_t)(m0 + a_m) * lda + k0 + a_k);
        As[a_k + 0][a_m] = av.x;
        As[a_k + 1][a_m] = av.y;
        As[a_k + 2][a_m] = av.z;
        As[a_k + 3][a_m] = av.w;
        float4 bv = make_float4(0.f, 0.f, 0.f, 0.f);
        if (n0 + b_n < N)
            bv = *(const float4*)(W + (size_t)(k0 + b_k) * ldb + n0 + b_n);
        *(float4*)&Bs[b_k][b_n] = bv;
        __syncthreads();

        #pragma unroll
        for (int k = 0; k < BK; k++) {
            float4 a = *(const float4*)&As[k][ty * 4];
            float4 b = *(const float4*)&Bs[k][tx * 4];
            float ar[4] = {a.x, a.y, a.z, a.w};
            float br[4] = {b.x, b.y, b.z, b.w};
            #pragma unroll
            for (int i = 0; i < 4; i++)
                #pragma unroll
                for (int j = 0; j < 4; j++)
                    acc[i][j] = fmaf(ar[i], br[j], acc[i][j]);
        }
        __syncthreads();
    }

    #pragma unroll
    for (int i = 0; i < 4; i++) {
        int row = m0 + ty * 4 + i;
        #pragma unroll
        for (int j = 0; j < 4; j++) {
            int col = n0 + tx * 4 + j;
            if (col < N)
                atomicAdd(C + (size_t)row * ldc + col, acc[i][j]);
        }
    }
}

// ---------------- depthwise causal conv (k=4) + SiLU ----------------
__global__ __launch_bounds__(256) void conv_silu_kernel(const float* __restrict__ w,
                                                        const float* __restrict__ cb) {
    int idx = blockIdx.x * blockDim.x + threadIdx.x;
    if (idx >= M_ROWS * DIN) return;
    int d = idx & (DIN - 1);
    int row = idx >> 11;
    int l = row & (L_SZ - 1);
    float acc = cb[d];
    const float* up = g_xz + (size_t)row * (2 * DIN) + d;
    const float* wd = w + d * 4;
    #pragma unroll
    for (int j = 0; j < 4; j++) {
        int ll = l - 3 + j;
        if (ll >= 0) acc = fmaf(wd[j], up[(j - 3) * (2 * DIN)], acc);
    }
    g_uc[idx] = acc / (1.f + __expf(-acc));
}

// ---------------- selective scan ----------------
__global__ __launch_bounds__(128) void scan_kernel(const float* __restrict__ A_log,
                                                   const float* __restrict__ Dp) {
    int warp = blockIdx.x * (blockDim.x >> 5) + (threadIdx.x >> 5);
    int lane = threadIdx.x & 31;
    int half = lane >> 4;
    int n = lane & 15;
    int ch = warp * 2 + half;
    int b = ch >> 11;
    int d = ch & (DIN - 1);

    float A  = -__expf(A_log[d * NST + n]);
    float Dd = Dp[d];
    float h = 0.f;

    const float* delta_p = g_delta + (size_t)b * L_SZ * DIN + d;
    const float* u_p     = g_uc    + (size_t)b * L_SZ * DIN + d;
    const float* bc_p    = g_dbc   + (size_t)b * L_SZ * XPROJ_N;
    const float* z_p     = g_xz    + (size_t)b * L_SZ * (2 * DIN) + DIN + d;
    float*       y_p     = g_yz    + (size_t)b * L_SZ * DIN + d;

    #pragma unroll 2
    for (int l = 0; l < L_SZ; l++) {
        float dl = delta_p[(size_t)l * DIN];
        float u  = u_p[(size_t)l * DIN];
        float Bv = bc_p[(size_t)l * XPROJ_N + DTR + n];
        float Cv = bc_p[(size_t)l * XPROJ_N + DTR + NST + n];
        h = fmaf(__expf(dl * A), h, (dl * u) * Bv);
        float p = h * Cv;
        p += __shfl_xor_sync(0xffffffffu, p, 8);
        p += __shfl_xor_sync(0xffffffffu, p, 4);
        p += __shfl_xor_sync(0xffffffffu, p, 2);
        p += __shfl_xor_sync(0xffffffffu, p, 1);
        if (n == 0) {
            float y = p + u * Dd;
            float z = z_p[(size_t)l * (2 * DIN)];
            y_p[(size_t)l * DIN] = y * (z / (1.f + __expf(-z)));
        }
    }
}

// ---------------- launch ----------------
extern "C" void kernel_launch(void* const* d_in, const int* in_sizes, int n_in,
                              void* d_out, int out_size) {
    const float* x         = (const float*)d_in[0];
    const float* in_proj_w = (const float*)d_in[1];
    const float* conv_w    = (const float*)d_in[2];
    const float* conv_b    = (const float*)d_in[3];
    const float* x_proj_w  = (const float*)d_in[4];
    const float* dt_proj_w = (const float*)d_in[5];
    const float* dt_proj_b = (const float*)d_in[6];
    const float* A_log     = (const float*)d_in[7];
    const float* Dp        = (const float*)d_in[8];
    const float* out_proj_w= (const float*)d_in[9];
    const float* ln_g      = (const float*)d_in[10];
    const float* ln_b      = (const float*)d_in[11];
    float* out = (float*)d_out;

    float *p_xz, *p_uc, *p_dbc, *p_delta, *p_yz;
    cudaGetSymbolAddress((void**)&p_xz,    g_xz);
    cudaGetSymbolAddress((void**)&p_uc,    g_uc);
    cudaGetSymbolAddress((void**)&p_dbc,   g_dbc);
    cudaGetSymbolAddress((void**)&p_delta, g_delta);
    cudaGetSymbolAddress((void**)&p_yz,    g_yz);
    __nv_bfloat16 *pA1, *pB1, *pAdt, *pBdt, *pAy, *pBo;
    cudaGetSymbolAddress((void**)&pA1,  gA1);
    cudaGetSymbolAddress((void**)&pB1,  gB1);
    cudaGetSymbolAddress((void**)&pAdt, gAdt);
    cudaGetSymbolAddress((void**)&pBdt, gBdt);
    cudaGetSymbolAddress((void**)&pAy,  gAy);
    cudaGetSymbolAddress((void**)&pBo,  gBo);

    // 0. zero x_proj accumulator
    zero_kernel<<<(M_ROWS * XPROJ_N / 4 + 255) / 256, 256>>>(p_dbc, M_ROWS * XPROJ_N / 4);

    // 1. weight conversions (transpose + split-bf16 expand)
    wexpT<<<dim3((2*DIN)/32, DM/32),   256>>>(in_proj_w,  pB1, DM,  2*DIN);
    wexpT<<<dim3(DIN/32,     DTR/32),  256>>>(dt_proj_w,  pBdt, DTR, DIN);
    wexpT<<<dim3(DM/32,      DIN/32),  256>>>(out_proj_w, pBo, DIN, DM);

    // 2. layernorm + A expand
    ln_expand<<<M_ROWS, 256>>>(x, ln_g, ln_b);

    // 3. xz = xn @ in_proj_w  (mma: [4096,3072] @ [4096,3072]^T)
    gemm_mma<0><<<dim3((2*DIN)/128, M_ROWS/128), 256>>>(
        pA1, pB1, 3*DM, p_xz, 2*DIN, nullptr, 0);

    // 4. uc = silu(conv(u))
    conv_silu_kernel<<<(M_ROWS * DIN + 255) / 256, 256>>>(conv_w, conv_b);

    // 5. dbc += uc @ x_proj_w (fp32 split-K)
    {
        dim3 grid((XPROJ_N + 63) / 64, M_ROWS / 64, 8);
        gemm64_splitk<<<grid, 256>>>(p_uc, DIN, x_proj_w, XPROJ_N,
                                     p_dbc, XPROJ_N, XPROJ_N, DIN / 8);
    }

    // 6. expand dt slice; delta = softplus(dt @ dt_proj_w + b)
    aexp<<<(M_ROWS * (DTR/4) + 255) / 256, 256>>>(p_dbc, XPROJ_N, pAdt, DTR, M_ROWS);
    gemm_mma<1><<<dim3(DIN/128, M_ROWS/128), 256>>>(
        pAdt, pBdt, 3*DTR, p_delta, DIN, dt_proj_b, 0);

    // 7. selective scan + gate
    scan_kernel<<<(B_SZ * DIN / 2) / 4, 128>>>(A_log, Dp);

    // 8. expand yz; out = yz @ out_proj_w + x
    aexp<<<(M_ROWS * (DIN/4) + 255) / 256, 256>>>(p_yz, DIN, pAy, DIN, M_ROWS);
    gemm_mma<2><<<dim3(DM/128, M_ROWS/128), 256>>>(
        pAy, pBo, 3*DIN, out, DM, x, DM);
}

// round 9
// speedup vs baseline: 1.8446x; 1.3120x over previous
#include <cuda_runtime.h>
#include <cuda_bf16.h>
#include <math.h>
#include <stdint.h>

// ---------------- problem constants ----------------
#define B_SZ  2
#define L_SZ  2048
#define DM    1024
#define DIN   2048
#define NST   16
#define DTR   64
#define M_ROWS (B_SZ * L_SZ)   // 4096
#define XPROJ_N (DTR + 2*NST)  // 96

// ---------------- scratch ----------------
__device__ __align__(256) float g_xz[M_ROWS * 2 * DIN];
__device__ __align__(256) float g_uc[M_ROWS * DIN];
__device__ __align__(256) float g_dbc[M_ROWS * XPROJ_N];
__device__ __align__(256) float g_delta[M_ROWS * DIN];
__device__ __align__(256) float g_yz[M_ROWS * DIN];

// split-bf16 expanded operands
__device__ __align__(256) __nv_bfloat16 gA1 [M_ROWS * 3 * DM];
__device__ __align__(256) __nv_bfloat16 gB1 [(2*DIN) * 3 * DM];
__device__ __align__(256) __nv_bfloat16 gAdt[M_ROWS * 3 * DTR];
__device__ __align__(256) __nv_bfloat16 gBdt[DIN * 3 * DTR];
__device__ __align__(256) __nv_bfloat16 gAy [M_ROWS * 3 * DIN];
__device__ __align__(256) __nv_bfloat16 gBo [DM * 3 * DIN];

// ---------------- PTX helpers (all baseline sm_80/75 features) ----------------
__device__ __forceinline__ uint32_t smem_u32(const void* p) {
    uint32_t a;
    asm("{ .reg .u64 t; cvta.to.shared.u64 t, %1; cvt.u32.u64 %0, t; }" : "=r"(a) : "l"(p));
    return a;
}
#define CP_ASYNC16(dst, src) \
    asm volatile("cp.async.cg.shared.global [%0], [%1], 16;" :: "r"(dst), "l"(src) : "memory")
#define CP_COMMIT() asm volatile("cp.async.commit_group;" ::: "memory")
#define CP_WAIT(n)  asm volatile("cp.async.wait_group %0;" :: "n"(n) : "memory")
#define LDSM_X4(r, a) \
    asm volatile("ldmatrix.sync.aligned.m8n8.x4.shared.b16 {%0,%1,%2,%3}, [%4];" \
        : "=r"((r)[0]), "=r"((r)[1]), "=r"((r)[2]), "=r"((r)[3]) : "r"(a))
#define MMA16816(c, a, b0, b1) \
    asm volatile("mma.sync.aligned.m16n8k16.row.col.f32.bf16.bf16.f32 " \
        "{%0,%1,%2,%3}, {%4,%5,%6,%7}, {%8,%9}, {%0,%1,%2,%3};" \
        : "+f"((c)[0]), "+f"((c)[1]), "+f"((c)[2]), "+f"((c)[3]) \
        : "r"((a)[0]), "r"((a)[1]), "r"((a)[2]), "r"((a)[3]), "r"(b0), "r"(b1))

// ---------------- ln + expand:  x -> [hi|hi|lo] bf16 ----------------
__global__ __launch_bounds__(256) void ln_expand(const float* __restrict__ x,
                                                 const float* __restrict__ g,
                                                 const float* __restrict__ bb) {
    int row = blockIdx.x;
    int t = threadIdx.x;
    float4 v = ((const float4*)(x + (size_t)row * DM))[t];
    float s  = v.x + v.y + v.z + v.w;
    float sq = v.x*v.x + v.y*v.y + v.z*v.z + v.w*v.w;
    #pragma unroll
    for (int o = 16; o > 0; o >>= 1) {
        s  += __shfl_xor_sync(0xffffffffu, s, o);
        sq += __shfl_xor_sync(0xffffffffu, sq, o);
    }
    __shared__ float rs[8], rq[8];
    int wid = t >> 5, lane = t & 31;
    if (lane == 0) { rs[wid] = s; rq[wid] = sq; }
    __syncthreads();
    float S = 0.f, Q = 0.f;
    #pragma unroll
    for (int i = 0; i < 8; i++) { S += rs[i]; Q += rq[i]; }
    float mean = S * (1.0f / DM);
    float var  = Q * (1.0f / DM) - mean * mean;
    float rstd = rsqrtf(var + 1e-5f);
    float4 gg = ((const float4*)g)[t];
    float4 bv = ((const float4*)bb)[t];
    float o[4];
    o[0] = (v.x - mean) * rstd * gg.x + bv.x;
    o[1] = (v.y - mean) * rstd * gg.y + bv.y;
    o[2] = (v.z - mean) * rstd * gg.z + bv.z;
    o[3] = (v.w - mean) * rstd * gg.w + bv.w;
    __nv_bfloat16 hi[4], lo[4];
    #pragma unroll
    for (int i = 0; i < 4; i++) {
        hi[i] = __float2bfloat16(o[i]);
        lo[i] = __float2bfloat16(o[i] - __bfloat162float(hi[i]));
    }
    size_t base = (size_t)row * (3 * DM);
    int k = t * 4;
    *(uint64_t*)(gA1 + base + k)          = *(uint64_t*)hi;
    *(uint64_t*)(gA1 + base + DM + k)     = *(uint64_t*)hi;
    *(uint64_t*)(gA1 + base + 2 * DM + k) = *(uint64_t*)lo;
}

// ---------------- generic A expand: A[M,K] (stride ldin) -> [hi|hi|lo] ----------------
__global__ __launch_bounds__(256) void aexp(const float* __restrict__ A, int ldin,
                                            __nv_bfloat16* __restrict__ Ap, int K, int M) {
    int kq = K >> 2;
    int idx = blockIdx.x * blockDim.x + threadIdx.x;
    if (idx >= M * kq) return;
    int m = idx / kq, k = (idx - m * kq) * 4;
    float4 v = *(const float4*)(A + (size_t)m * ldin + k);
    float o[4] = {v.x, v.y, v.z, v.w};
    __nv_bfloat16 hi[4], lo[4];
    #pragma unroll
    for (int i = 0; i < 4; i++) {
        hi[i] = __float2bfloat16(o[i]);
        lo[i] = __float2bfloat16(o[i] - __bfloat162float(hi[i]));
    }
    size_t base = (size_t)m * (3 * K);
    *(uint64_t*)(Ap + base + k)         = *(uint64_t*)hi;
    *(uint64_t*)(Ap + base + K + k)     = *(uint64_t*)hi;
    *(uint64_t*)(Ap + base + 2 * K + k) = *(uint64_t*)lo;
}

// ---------------- weight transpose+expand: W[K,N] -> Bp[N,3K] = [hi|lo|hi] ----------------
__global__ __launch_bounds__(256) void wexpT(const float* __restrict__ W,
                                             __nv_bfloat16* __restrict__ Bp, int K, int N) {
    __shared__ float tile[32][33];
    int k0 = blockIdx.y * 32, n0 = blockIdx.x * 32;
    int tx = threadIdx.x & 31, ty = threadIdx.x >> 5;
    #pragma unroll
    for (int i = 0; i < 32; i += 8)
        tile[ty + i][tx] = W[(size_t)(k0 + ty + i) * N + n0 + tx];
    __syncthreads();
    #pragma unroll
    for (int i = 0; i < 32; i += 8) {
        int n = n0 + ty + i;
        int k = k0 + tx;
        float v = tile[tx][ty + i];
        __nv_bfloat16 hi = __float2bfloat16(v);
        __nv_bfloat16 lo = __float2bfloat16(v - __bfloat162float(hi));
        size_t base = (size_t)n * (3 * K);
        Bp[base + k]         = hi;
        Bp[base + K + k]     = lo;
        Bp[base + 2 * K + k] = hi;
    }
}

// ---------------- mma.sync bf16 GEMM: C[M,N] = A'[M,K3] @ B'[N,K3]^T ----------------
// Block 128x128, BK=32, 8 warps (4m x 2n), warp tile 32x64. 2-stage (R6-proven).
template <int EPI>
__global__ __launch_bounds__(256, 2) void gemm_mma(
    const __nv_bfloat16* __restrict__ Ag,
    const __nv_bfloat16* __restrict__ Bg,
    int K3, float* __restrict__ C, int ldc,
    const float* __restrict__ extra, int lde)
{
    __shared__ __align__(1024) char smA[2][8192];
    __shared__ __align__(1024) char smB[2][8192];

    int tid = threadIdx.x, lane = tid & 31, wid = tid >> 5;
    int m0 = blockIdx.y * 128, n0 = blockIdx.x * 128;
    int wm = (wid & 3) * 32, wn = (wid >> 2) * 64;

    float c[2][8][4];
    #pragma unroll
    for (int t = 0; t < 2; t++)
        #pragma unroll
        for (int j = 0; j < 8; j++)
            #pragma unroll
            for (int q = 0; q < 4; q++) c[t][j][q] = 0.f;

    const __nv_bfloat16* Arow = Ag + (size_t)m0 * K3;
    const __nv_bfloat16* Brow = Bg + (size_t)n0 * K3;

    // copy mapping: 512 chunks of 16B per tile; thread handles chunks tid, tid+256
    int r0 = tid >> 2,        g0 = tid & 3;
    int r1 = (tid + 256) >> 2, g1 = tid & 3;  // (tid+256)&3 == tid&3
    uint32_t oA0 = (uint32_t)(r0 * 64 + ((g0 * 16) ^ ((r0 & 6) << 3)));
    uint32_t oA1 = (uint32_t)(r1 * 64 + ((g1 * 16) ^ ((r1 & 6) << 3)));
    uint32_t sA[2] = { smem_u32(&smA[0][0]), smem_u32(&smA[1][0]) };
    uint32_t sB[2] = { smem_u32(&smB[0][0]), smem_u32(&smB[1][0]) };

    auto issue = [&](int buf, int kt) {
        CP_ASYNC16(sA[buf] + oA0, Arow + (size_t)r0 * K3 + kt + g0 * 8);
        CP_ASYNC16(sA[buf] + oA1, Arow + (size_t)r1 * K3 + kt + g1 * 8);
        CP_ASYNC16(sB[buf] + oA0, Brow + (size_t)r0 * K3 + kt + g0 * 8);
        CP_ASYNC16(sB[buf] + oA1, Brow + (size_t)r1 * K3 + kt + g1 * 8);
        CP_COMMIT();
    };

    // ldmatrix per-lane geometry
    int arow = lane & 15;                       // row within m16 tile
    uint32_t akx = (lane & 16) ? 16u : 0u;      // +8 cols (16B)
    int brow = (lane & 7) + ((lane & 16) ? 8 : 0);
    uint32_t bkx = (lane & 8) ? 16u : 0u;

    int nIter = K3 / 32;
    issue(0, 0);

    for (int it = 0; it < nIter; it++) {
        int cur = it & 1;
        if (it + 1 < nIter) { issue(cur ^ 1, (it + 1) * 32); CP_WAIT(1); }
        else                { CP_WAIT(0); }
        __syncthreads();

        #pragma unroll
        for (int ks = 0; ks < 2; ks++) {
            uint32_t af[2][4];
            #pragma unroll
            for (int t = 0; t < 2; t++) {
                int row = wm + 16 * t + arow;
                uint32_t addr = sA[cur] + row * 64 + (((uint32_t)ks * 32 + akx) ^ ((row & 6) << 3));
                LDSM_X4(af[t], addr);
            }
            uint32_t bf[4][4];
            #pragma unroll
            for (int p = 0; p < 4; p++) {
                int row = wn + 16 * p + brow;
                uint32_t addr = sB[cur] + row * 64 + (((uint32_t)ks * 32 + bkx) ^ ((row & 6) << 3));
                LDSM_X4(bf[p], addr);
            }
            #pragma unroll
            for (int t = 0; t < 2; t++)
                #pragma unroll
                for (int j = 0; j < 8; j++)
                    MMA16816(c[t][j], af[t], bf[j >> 1][2 * (j & 1)], bf[j >> 1][2 * (j & 1) + 1]);
        }
        __syncthreads();
    }

    // ---- epilogue: direct fragment stores (float2) ----
    int rbase = m0 + wm + (lane >> 2);
    int cbase = n0 + wn + (lane & 3) * 2;
    #pragma unroll
    for (int t = 0; t < 2; t++) {
        #pragma unroll
        for (int j = 0; j < 8; j++) {
            int col = cbase + 8 * j;
            #pragma unroll
            for (int h = 0; h < 2; h++) {       // h=0: rows, h=1: rows+8
                int row = rbase + 16 * t + 8 * h;
                float v0 = c[t][j][2 * h], v1 = c[t][j][2 * h + 1];
                if (EPI == 1) {
                    float t0 = v0 + extra[col],     t1 = v1 + extra[col + 1];
                    v0 = (t0 > 20.f) ? t0 : log1pf(__expf(t0));
                    v1 = (t1 > 20.f) ? t1 : log1pf(__expf(t1));
                } else if (EPI == 2) {
                    v0 += extra[(size_t)row * lde + col];
                    v1 += extra[(size_t)row * lde + col + 1];
                }
                float2 st = make_float2(v0, v1);
                *(float2*)(C + (size_t)row * ldc + col) = st;
            }
        }
    }
}

// ---------------- zero kernel ----------------
__global__ __launch_bounds__(256) void zero_kernel(float* p, int n4) {
    int i = blockIdx.x * blockDim.x + threadIdx.x;
    if (i < n4) ((float4*)p)[i] = make_float4(0.f, 0.f, 0.f, 0.f);
}

// ---------------- x_proj: 64x64 split-K fp32 GEMM, atomic epilogue ----------------
__global__ __launch_bounds__(256) void gemm64_splitk(
    const float* __restrict__ A, int lda,
    const float* __restrict__ W, int ldb,
    float* __restrict__ C, int ldc,
    int N, int KS)
{
    const int BK = 16;
    __shared__ __align__(16) float As[BK][64];
    __shared__ __align__(16) float Bs[BK][64];

    int tid = threadIdx.x;
    int tx = tid & 15, ty = tid >> 4;
    int m0 = blockIdx.y * 64;
    int n0 = blockIdx.x * 64;
    int koff = blockIdx.z * KS;

    int a_m = tid >> 2;
    int a_k = (tid & 3) * 4;
    int b_k = tid >> 4;
    int b_n = (tid & 15) * 4;

    float acc[4][4];
    #pragma unroll
    for (int i = 0; i < 4; i++)
        #pragma unroll
        for (int j = 0; j < 4; j++) acc[i][j] = 0.f;

    for (int k0 = koff; k0 < koff + KS; k0 += BK) {
        float4 av = *(const float4*)(A + (size_t)(m0 + a_m) * lda + k0 + a_k);
        As[a_k + 0][a_m] = av.x;
        As[a_k + 1][a_m] = av.y;
        As[a_k + 2][a_m] = av.z;
        As[a_k + 3][a_m] = av.w;
        float4 bv = make_float4(0.f, 0.f, 0.f, 0.f);
        if (n0 + b_n < N)
            bv = *(const float4*)(W + (size_t)(k0 + b_k) * ldb + n0 + b_n);
        *(float4*)&Bs[b_k][b_n] = bv;
        __syncthreads();

        #pragma unroll
        for (int k = 0; k < BK; k++) {
            float4 a = *(const float4*)&As[k][ty * 4];
            float4 b = *(const float4*)&Bs[k][tx * 4];
            float ar[4] = {a.x, a.y, a.z, a.w};
            float br[4] = {b.x, b.y, b.z, b.w};
            #pragma unroll
            for (int i = 0; i < 4; i++)
                #pragma unroll
                for (int j = 0; j < 4; j++)
                    acc[i][j] = fmaf(ar[i], br[j], acc[i][j]);
        }
        __syncthreads();
    }

    #pragma unroll
    for (int i = 0; i < 4; i++) {
        int row = m0 + ty * 4 + i;
        #pragma unroll
        for (int j = 0; j < 4; j++) {
            int col = n0 + tx * 4 + j;
            if (col < N)
                atomicAdd(C + (size_t)row * ldc + col, acc[i][j]);
        }
    }
}

// ---------------- depthwise causal conv (k=4) + SiLU ----------------
__global__ __launch_bounds__(256) void conv_silu_kernel(const float* __restrict__ w,
                                                        const float* __restrict__ cb) {
    int idx = blockIdx.x * blockDim.x + threadIdx.x;
    if (idx >= M_ROWS * DIN) return;
    int d = idx & (DIN - 1);
    int row = idx >> 11;
    int l = row & (L_SZ - 1);
    float acc = cb[d];
    const float* up = g_xz + (size_t)row * (2 * DIN) + d;
    const float* wd = w + d * 4;
    #pragma unroll
    for (int j = 0; j < 4; j++) {
        int ll = l - 3 + j;
        if (ll >= 0) acc = fmaf(wd[j], up[(j - 3) * (2 * DIN)], acc);
    }
    g_uc[idx] = acc / (1.f + __expf(-acc));
}

// ---------------- selective scan: 8-step load batching for MLP ----------------
__global__ __launch_bounds__(128) void scan_kernel(const float* __restrict__ A_log,
                                                   const float* __restrict__ Dp) {
    int warp = blockIdx.x * (blockDim.x >> 5) + (threadIdx.x >> 5);
    int lane = threadIdx.x & 31;
    int half = lane >> 4;
    int n = lane & 15;
    int ch = warp * 2 + half;
    int b = ch >> 11;
    int d = ch & (DIN - 1);

    float A  = -__expf(A_log[d * NST + n]);
    float Dd = Dp[d];
    float h = 0.f;

    const float* delta_p = g_delta + (size_t)b * L_SZ * DIN + d;
    const float* u_p     = g_uc    + (size_t)b * L_SZ * DIN + d;
    const float* bc_p    = g_dbc   + (size_t)b * L_SZ * XPROJ_N;
    const float* z_p     = g_xz    + (size_t)b * L_SZ * (2 * DIN) + DIN + d;
    float*       y_p     = g_yz    + (size_t)b * L_SZ * DIN + d;

    for (int l0 = 0; l0 < L_SZ; l0 += 8) {
        float dl[8], uu[8], Bv[8], Cv[8];
        #pragma unroll
        for (int j = 0; j < 8; j++) {
            size_t l = l0 + j;
            dl[j] = delta_p[l * DIN];
            uu[j] = u_p[l * DIN];
            Bv[j] = bc_p[l * XPROJ_N + DTR + n];
            Cv[j] = bc_p[l * XPROJ_N + DTR + NST + n];
        }
        float p[8];
        #pragma unroll
        for (int j = 0; j < 8; j++) {
            h = fmaf(__expf(dl[j] * A), h, (dl[j] * uu[j]) * Bv[j]);
            p[j] = h * Cv[j];
        }
        #pragma unroll
        for (int j = 0; j < 8; j++) {
            float q = p[j];
            q += __shfl_xor_sync(0xffffffffu, q, 8);
            q += __shfl_xor_sync(0xffffffffu, q, 4);
            q += __shfl_xor_sync(0xffffffffu, q, 2);
            q += __shfl_xor_sync(0xffffffffu, q, 1);
            if (n == 0) {
                float y = q + uu[j] * Dd;
                float z = z_p[(size_t)(l0 + j) * (2 * DIN)];
                y_p[(size_t)(l0 + j) * DIN] = y * (z / (1.f + __expf(-z)));
            }
        }
    }
}

// ---------------- launch ----------------
extern "C" void kernel_launch(void* const* d_in, const int* in_sizes, int n_in,
                              void* d_out, int out_size) {
    const float* x         = (const float*)d_in[0];
    const float* in_proj_w = (const float*)d_in[1];
    const float* conv_w    = (const float*)d_in[2];
    const float* conv_b    = (const float*)d_in[3];
    const float* x_proj_w  = (const float*)d_in[4];
    const float* dt_proj_w = (const float*)d_in[5];
    const float* dt_proj_b = (const float*)d_in[6];
    const float* A_log     = (const float*)d_in[7];
    const float* Dp        = (const float*)d_in[8];
    const float* out_proj_w= (const float*)d_in[9];
    const float* ln_g      = (const float*)d_in[10];
    const float* ln_b      = (const float*)d_in[11];
    float* out = (float*)d_out;

    float *p_xz, *p_uc, *p_dbc, *p_delta, *p_yz;
    cudaGetSymbolAddress((void**)&p_xz,    g_xz);
    cudaGetSymbolAddress((void**)&p_uc,    g_uc);
    cudaGetSymbolAddress((void**)&p_dbc,   g_dbc);
    cudaGetSymbolAddress((void**)&p_delta, g_delta);
    cudaGetSymbolAddress((void**)&p_yz,    g_yz);
    __nv_bfloat16 *pA1, *pB1, *pAdt, *pBdt, *pAy, *pBo;
    cudaGetSymbolAddress((void**)&pA1,  gA1);
    cudaGetSymbolAddress((void**)&pB1,  gB1);
    cudaGetSymbolAddress((void**)&pAdt, gAdt);
    cudaGetSymbolAddress((void**)&pBdt, gBdt);
    cudaGetSymbolAddress((void**)&pAy,  gAy);
    cudaGetSymbolAddress((void**)&pBo,  gBo);

    // 0. zero x_proj accumulator
    zero_kernel<<<(M_ROWS * XPROJ_N / 4 + 255) / 256, 256>>>(p_dbc, M_ROWS * XPROJ_N / 4);

    // 1. weight conversions
    wexpT<<<dim3((2*DIN)/32, DM/32),   256>>>(in_proj_w,  pB1, DM,  2*DIN);
    wexpT<<<dim3(DIN/32,     DTR/32),  256>>>(dt_proj_w,  pBdt, DTR, DIN);
    wexpT<<<dim3(DM/32,      DIN/32),  256>>>(out_proj_w, pBo, DIN, DM);

    // 2. layernorm + A expand
    ln_expand<<<M_ROWS, 256>>>(x, ln_g, ln_b);

    // 3. xz = xn @ in_proj_w
    gemm_mma<0><<<dim3((2*DIN)/128, M_ROWS/128), 256>>>(
        pA1, pB1, 3*DM, p_xz, 2*DIN, nullptr, 0);

    // 4. uc = silu(conv(u))
    conv_silu_kernel<<<(M_ROWS * DIN + 255) / 256, 256>>>(conv_w, conv_b);

    // 5. dbc += uc @ x_proj_w (fp32 split-K)
    {
        dim3 grid((XPROJ_N + 63) / 64, M_ROWS / 64, 8);
        gemm64_splitk<<<grid, 256>>>(p_uc, DIN, x_proj_w, XPROJ_N,
                                     p_dbc, XPROJ_N, XPROJ_N, DIN / 8);
    }

    // 6. expand dt slice; delta = softplus(dt @ dt_proj_w + b)
    aexp<<<(M_ROWS * (DTR/4) + 255) / 256, 256>>>(p_dbc, XPROJ_N, pAdt, DTR, M_ROWS);
    gemm_mma<1><<<dim3(DIN/128, M_ROWS/128), 256>>>(
        pAdt, pBdt, 3*DTR, p_delta, DIN, dt_proj_b, 0);

    // 7. selective scan + gate
    scan_kernel<<<(B_SZ * DIN / 2) / 4, 128>>>(A_log, Dp);

    // 8. expand yz; out = yz @ out_proj_w + x
    aexp<<<(M_ROWS * (DIN/4) + 255) / 256, 256>>>(p_yz, DIN, pAy, DIN, M_ROWS);
    gemm_mma<2><<<dim3(DM/128, M_ROWS/128), 256>>>(
        pAy, pBo, 3*DIN, out, DM, x, DM);
}

// round 10
// speedup vs baseline: 2.0005x; 1.0845x over previous
#include <cuda_runtime.h>
#include <cuda_fp16.h>
#include <math.h>
#include <stdint.h>

// ---------------- problem constants ----------------
#define B_SZ  2
#define L_SZ  2048
#define DM    1024
#define DIN   2048
#define NST   16
#define DTR   64
#define M_ROWS (B_SZ * L_SZ)   // 4096
#define XPROJ_N (DTR + 2*NST)  // 96

// ---------------- scratch ----------------
__device__ __align__(256) float g_xz[M_ROWS * 2 * DIN];
__device__ __align__(256) float g_uc[M_ROWS * DIN];
__device__ __align__(256) float g_dbc[M_ROWS * XPROJ_N];
__device__ __align__(256) float g_delta[M_ROWS * DIN];
__device__ __align__(256) float g_yz[M_ROWS * DIN];

// split-fp16 expanded operands (A-side: [hi|lo], B-side: [hi|hi]) — K' = 2K
__device__ __align__(256) __half gA1 [M_ROWS * 2 * DM];
__device__ __align__(256) __half gB1 [(2*DIN) * 2 * DM];
__device__ __align__(256) __half gAdt[M_ROWS * 2 * DTR];
__device__ __align__(256) __half gBdt[DIN * 2 * DTR];
__device__ __align__(256) __half gAy [M_ROWS * 2 * DIN];
__device__ __align__(256) __half gBo [DM * 2 * DIN];

// ---------------- PTX helpers (all baseline sm_80/75 features) ----------------
__device__ __forceinline__ uint32_t smem_u32(const void* p) {
    uint32_t a;
    asm("{ .reg .u64 t; cvta.to.shared.u64 t, %1; cvt.u32.u64 %0, t; }" : "=r"(a) : "l"(p));
    return a;
}
#define CP_ASYNC16(dst, src) \
    asm volatile("cp.async.cg.shared.global [%0], [%1], 16;" :: "r"(dst), "l"(src) : "memory")
#define CP_COMMIT() asm volatile("cp.async.commit_group;" ::: "memory")
#define CP_WAIT(n)  asm volatile("cp.async.wait_group %0;" :: "n"(n) : "memory")
#define LDSM_X4(r, a) \
    asm volatile("ldmatrix.sync.aligned.m8n8.x4.shared.b16 {%0,%1,%2,%3}, [%4];" \
        : "=r"((r)[0]), "=r"((r)[1]), "=r"((r)[2]), "=r"((r)[3]) : "r"(a))
#define MMA16816(c, a, b0, b1) \
    asm volatile("mma.sync.aligned.m16n8k16.row.col.f32.f16.f16.f32 " \
        "{%0,%1,%2,%3}, {%4,%5,%6,%7}, {%8,%9}, {%0,%1,%2,%3};" \
        : "+f"((c)[0]), "+f"((c)[1]), "+f"((c)[2]), "+f"((c)[3]) \
        : "r"((a)[0]), "r"((a)[1]), "r"((a)[2]), "r"((a)[3]), "r"(b0), "r"(b1))

// ---------------- ln + expand:  x -> [hi|lo] fp16 ----------------
__global__ __launch_bounds__(256) void ln_expand(const float* __restrict__ x,
                                                 const float* __restrict__ g,
                                                 const float* __restrict__ bb) {
    int row = blockIdx.x;
    int t = threadIdx.x;
    float4 v = ((const float4*)(x + (size_t)row * DM))[t];
    float s  = v.x + v.y + v.z + v.w;
    float sq = v.x*v.x + v.y*v.y + v.z*v.z + v.w*v.w;
    #pragma unroll
    for (int o = 16; o > 0; o >>= 1) {
        s  += __shfl_xor_sync(0xffffffffu, s, o);
        sq += __shfl_xor_sync(0xffffffffu, sq, o);
    }
    __shared__ float rs[8], rq[8];
    int wid = t >> 5, lane = t & 31;
    if (lane == 0) { rs[wid] = s; rq[wid] = sq; }
    __syncthreads();
    float S = 0.f, Q = 0.f;
    #pragma unroll
    for (int i = 0; i < 8; i++) { S += rs[i]; Q += rq[i]; }
    float mean = S * (1.0f / DM);
    float var  = Q * (1.0f / DM) - mean * mean;
    float rstd = rsqrtf(var + 1e-5f);
    float4 gg = ((const float4*)g)[t];
    float4 bv = ((const float4*)bb)[t];
    float o[4];
    o[0] = (v.x - mean) * rstd * gg.x + bv.x;
    o[1] = (v.y - mean) * rstd * gg.y + bv.y;
    o[2] = (v.z - mean) * rstd * gg.z + bv.z;
    o[3] = (v.w - mean) * rstd * gg.w + bv.w;
    __half hi[4], lo[4];
    #pragma unroll
    for (int i = 0; i < 4; i++) {
        hi[i] = __float2half_rn(o[i]);
        lo[i] = __float2half_rn(o[i] - __half2float(hi[i]));
    }
    size_t base = (size_t)row * (2 * DM);
    int k = t * 4;
    *(uint64_t*)(gA1 + base + k)      = *(uint64_t*)hi;
    *(uint64_t*)(gA1 + base + DM + k) = *(uint64_t*)lo;
}

// ---------------- generic A expand: A[M,K] (stride ldin) -> [hi|lo] ----------------
__global__ __launch_bounds__(256) void aexp(const float* __restrict__ A, int ldin,
                                            __half* __restrict__ Ap, int K, int M) {
    int kq = K >> 2;
    int idx = blockIdx.x * blockDim.x + threadIdx.x;
    if (idx >= M * kq) return;
    int m = idx / kq, k = (idx - m * kq) * 4;
    float4 v = *(const float4*)(A + (size_t)m * ldin + k);
    float o[4] = {v.x, v.y, v.z, v.w};
    __half hi[4], lo[4];
    #pragma unroll
    for (int i = 0; i < 4; i++) {
        hi[i] = __float2half_rn(o[i]);
        lo[i] = __float2half_rn(o[i] - __half2float(hi[i]));
    }
    size_t base = (size_t)m * (2 * K);
    *(uint64_t*)(Ap + base + k)     = *(uint64_t*)hi;
    *(uint64_t*)(Ap + base + K + k) = *(uint64_t*)lo;
}

// ---------------- weight transpose+expand: W[K,N] -> Bp[N,2K] = [hi|hi] ----------------
__global__ __launch_bounds__(256) void wexpT(const float* __restrict__ W,
                                             __half* __restrict__ Bp, int K, int N) {
    __shared__ float tile[32][33];
    int k0 = blockIdx.y * 32, n0 = blockIdx.x * 32;
    int tx = threadIdx.x & 31, ty = threadIdx.x >> 5;
    #pragma unroll
    for (int i = 0; i < 32; i += 8)
        tile[ty + i][tx] = W[(size_t)(k0 + ty + i) * N + n0 + tx];
    __syncthreads();
    #pragma unroll
    for (int i = 0; i < 32; i += 8) {
        int n = n0 + ty + i;
        int k = k0 + tx;
        __half hi = __float2half_rn(tile[tx][ty + i]);
        size_t base = (size_t)n * (2 * K);
        Bp[base + k]     = hi;
        Bp[base + K + k] = hi;
    }
}

// ---------------- mma.sync fp16 GEMM: C[M,N] = A'[M,K2] @ B'[N,K2]^T ----------------
// Block 128x128, BK=32, 8 warps (4m x 2n), warp tile 32x64. 2-stage (proven).
template <int EPI>
__global__ __launch_bounds__(256, 2) void gemm_mma(
    const __half* __restrict__ Ag,
    const __half* __restrict__ Bg,
    int K3, float* __restrict__ C, int ldc,
    const float* __restrict__ extra, int lde)
{
    __shared__ __align__(1024) char smA[2][8192];
    __shared__ __align__(1024) char smB[2][8192];

    int tid = threadIdx.x, lane = tid & 31, wid = tid >> 5;
    int m0 = blockIdx.y * 128, n0 = blockIdx.x * 128;
    int wm = (wid & 3) * 32, wn = (wid >> 2) * 64;

    float c[2][8][4];
    #pragma unroll
    for (int t = 0; t < 2; t++)
        #pragma unroll
        for (int j = 0; j < 8; j++)
            #pragma unroll
            for (int q = 0; q < 4; q++) c[t][j][q] = 0.f;

    const __half* Arow = Ag + (size_t)m0 * K3;
    const __half* Brow = Bg + (size_t)n0 * K3;

    int r0 = tid >> 2,        g0 = tid & 3;
    int r1 = (tid + 256) >> 2, g1 = tid & 3;
    uint32_t oA0 = (uint32_t)(r0 * 64 + ((g0 * 16) ^ ((r0 & 6) << 3)));
    uint32_t oA1 = (uint32_t)(r1 * 64 + ((g1 * 16) ^ ((r1 & 6) << 3)));
    uint32_t sA[2] = { smem_u32(&smA[0][0]), smem_u32(&smA[1][0]) };
    uint32_t sB[2] = { smem_u32(&smB[0][0]), smem_u32(&smB[1][0]) };

    auto issue = [&](int buf, int kt) {
        CP_ASYNC16(sA[buf] + oA0, Arow + (size_t)r0 * K3 + kt + g0 * 8);
        CP_ASYNC16(sA[buf] + oA1, Arow + (size_t)r1 * K3 + kt + g1 * 8);
        CP_ASYNC16(sB[buf] + oA0, Brow + (size_t)r0 * K3 + kt + g0 * 8);
        CP_ASYNC16(sB[buf] + oA1, Brow + (size_t)r1 * K3 + kt + g1 * 8);
        CP_COMMIT();
    };

    int arow = lane & 15;
    uint32_t akx = (lane & 16) ? 16u : 0u;
    int brow = (lane & 7) + ((lane & 16) ? 8 : 0);
    uint32_t bkx = (lane & 8) ? 16u : 0u;

    int nIter = K3 / 32;
    issue(0, 0);

    for (int it = 0; it < nIter; it++) {
        int cur = it & 1;
        if (it + 1 < nIter) { issue(cur ^ 1, (it + 1) * 32); CP_WAIT(1); }
        else                { CP_WAIT(0); }
        __syncthreads();

        #pragma unroll
        for (int ks = 0; ks < 2; ks++) {
            uint32_t af[2][4];
            #pragma unroll
            for (int t = 0; t < 2; t++) {
                int row = wm + 16 * t + arow;
                uint32_t addr = sA[cur] + row * 64 + (((uint32_t)ks * 32 + akx) ^ ((row & 6) << 3));
                LDSM_X4(af[t], addr);
            }
            uint32_t bf[4][4];
            #pragma unroll
            for (int p = 0; p < 4; p++) {
                int row = wn + 16 * p + brow;
                uint32_t addr = sB[cur] + row * 64 + (((uint32_t)ks * 32 + bkx) ^ ((row & 6) << 3));
                LDSM_X4(bf[p], addr);
            }
            #pragma unroll
            for (int t = 0; t < 2; t++)
                #pragma unroll
                for (int j = 0; j < 8; j++)
                    MMA16816(c[t][j], af[t], bf[j >> 1][2 * (j & 1)], bf[j >> 1][2 * (j & 1) + 1]);
        }
        __syncthreads();
    }

    // ---- epilogue: direct fragment stores (float2) ----
    int rbase = m0 + wm + (lane >> 2);
    int cbase = n0 + wn + (lane & 3) * 2;
    #pragma unroll
    for (int t = 0; t < 2; t++) {
        #pragma unroll
        for (int j = 0; j < 8; j++) {
            int col = cbase + 8 * j;
            #pragma unroll
            for (int h = 0; h < 2; h++) {
                int row = rbase + 16 * t + 8 * h;
                float v0 = c[t][j][2 * h], v1 = c[t][j][2 * h + 1];
                if (EPI == 1) {
                    float t0 = v0 + extra[col],     t1 = v1 + extra[col + 1];
                    v0 = (t0 > 20.f) ? t0 : log1pf(__expf(t0));
                    v1 = (t1 > 20.f) ? t1 : log1pf(__expf(t1));
                } else if (EPI == 2) {
                    v0 += extra[(size_t)row * lde + col];
                    v1 += extra[(size_t)row * lde + col + 1];
                }
                float2 st = make_float2(v0, v1);
                *(float2*)(C + (size_t)row * ldc + col) = st;
            }
        }
    }
}

// ---------------- zero kernel ----------------
__global__ __launch_bounds__(256) void zero_kernel(float* p, int n4) {
    int i = blockIdx.x * blockDim.x + threadIdx.x;
    if (i < n4) ((float4*)p)[i] = make_float4(0.f, 0.f, 0.f, 0.f);
}

// ---------------- x_proj: 64x64 split-K fp32 GEMM, atomic epilogue ----------------
__global__ __launch_bounds__(256) void gemm64_splitk(
    const float* __restrict__ A, int lda,
    const float* __restrict__ W, int ldb,
    float* __restrict__ C, int ldc,
    int N, int KS)
{
    const int BK = 16;
    __shared__ __align__(16) float As[BK][64];
    __shared__ __align__(16) float Bs[BK][64];

    int tid = threadIdx.x;
    int tx = tid & 15, ty = tid >> 4;
    int m0 = blockIdx.y * 64;
    int n0 = blockIdx.x * 64;
    int koff = blockIdx.z * KS;

    int a_m = tid >> 2;
    int a_k = (tid & 3) * 4;
    int b_k = tid >> 4;
    int b_n = (tid & 15) * 4;

    float acc[4][4];
    #pragma unroll
    for (int i = 0; i < 4; i++)
        #pragma unroll
        for (int j = 0; j < 4; j++) acc[i][j] = 0.f;

    for (int k0 = koff; k0 < koff + KS; k0 += BK) {
        float4 av = *(const float4*)(A + (size_t)(m0 + a_m) * lda + k0 + a_k);
        As[a_k + 0][a_m] = av.x;
        As[a_k + 1][a_m] = av.y;
        As[a_k + 2][a_m] = av.z;
        As[a_k + 3][a_m] = av.w;
        float4 bv = make_float4(0.f, 0.f, 0.f, 0.f);
        if (n0 + b_n < N)
            bv = *(const float4*)(W + (size_t)(k0 + b_k) * ldb + n0 + b_n);
        *(float4*)&Bs[b_k][b_n] = bv;
        __syncthreads();

        #pragma unroll
        for (int k = 0; k < BK; k++) {
            float4 a = *(const float4*)&As[k][ty * 4];
            float4 b = *(const float4*)&Bs[k][tx * 4];
            float ar[4] = {a.x, a.y, a.z, a.w};
            float br[4] = {b.x, b.y, b.z, b.w};
            #pragma unroll
            for (int i = 0; i < 4; i++)
                #pragma unroll
                for (int j = 0; j < 4; j++)
                    acc[i][j] = fmaf(ar[i], br[j], acc[i][j]);
        }
        __syncthreads();
    }

    #pragma unroll
    for (int i = 0; i < 4; i++) {
        int row = m0 + ty * 4 + i;
        #pragma unroll
        for (int j = 0; j < 4; j++) {
            int col = n0 + tx * 4 + j;
            if (col < N)
                atomicAdd(C + (size_t)row * ldc + col, acc[i][j]);
        }
    }
}

// ---------------- depthwise causal conv (k=4) + SiLU ----------------
__global__ __launch_bounds__(256) void conv_silu_kernel(const float* __restrict__ w,
                                                        const float* __restrict__ cb) {
    int idx = blockIdx.x * blockDim.x + threadIdx.x;
    if (idx >= M_ROWS * DIN) return;
    int d = idx & (DIN - 1);
    int row = idx >> 11;
    int l = row & (L_SZ - 1);
    float acc = cb[d];
    const float* up = g_xz + (size_t)row * (2 * DIN) + d;
    const float* wd = w + d * 4;
    #pragma unroll
    for (int j = 0; j < 4; j++) {
        int ll = l - 3 + j;
        if (ll >= 0) acc = fmaf(wd[j], up[(j - 3) * (2 * DIN)], acc);
    }
    g_uc[idx] = acc / (1.f + __expf(-acc));
}

// ---------------- selective scan: 8-step load batching for MLP ----------------
__global__ __launch_bounds__(128) void scan_kernel(const float* __restrict__ A_log,
                                                   const float* __restrict__ Dp) {
    int warp = blockIdx.x * (blockDim.x >> 5) + (threadIdx.x >> 5);
    int lane = threadIdx.x & 31;
    int half = lane >> 4;
    int n = lane & 15;
    int ch = warp * 2 + half;
    int b = ch >> 11;
    int d = ch & (DIN - 1);

    float A  = -__expf(A_log[d * NST + n]);
    float Dd = Dp[d];
    float h = 0.f;

    const float* delta_p = g_delta + (size_t)b * L_SZ * DIN + d;
    const float* u_p     = g_uc    + (size_t)b * L_SZ * DIN + d;
    const float* bc_p    = g_dbc   + (size_t)b * L_SZ * XPROJ_N;
    const float* z_p     = g_xz    + (size_t)b * L_SZ * (2 * DIN) + DIN + d;
    float*       y_p     = g_yz    + (size_t)b * L_SZ * DIN + d;

    for (int l0 = 0; l0 < L_SZ; l0 += 8) {
        float dl[8], uu[8], Bv[8], Cv[8];
        #pragma unroll
        for (int j = 0; j < 8; j++) {
            size_t l = l0 + j;
            dl[j] = delta_p[l * DIN];
            uu[j] = u_p[l * DIN];
            Bv[j] = bc_p[l * XPROJ_N + DTR + n];
            Cv[j] = bc_p[l * XPROJ_N + DTR + NST + n];
        }
        float p[8];
        #pragma unroll
        for (int j = 0; j < 8; j++) {
            h = fmaf(__expf(dl[j] * A), h, (dl[j] * uu[j]) * Bv[j]);
            p[j] = h * Cv[j];
        }
        #pragma unroll
        for (int j = 0; j < 8; j++) {
            float q = p[j];
            q += __shfl_xor_sync(0xffffffffu, q, 8);
            q += __shfl_xor_sync(0xffffffffu, q, 4);
            q += __shfl_xor_sync(0xffffffffu, q, 2);
            q += __shfl_xor_sync(0xffffffffu, q, 1);
            if (n == 0) {
                float y = q + uu[j] * Dd;
                float z = z_p[(size_t)(l0 + j) * (2 * DIN)];
                y_p[(size_t)(l0 + j) * DIN] = y * (z / (1.f + __expf(-z)));
            }
        }
    }
}

// ---------------- launch ----------------
extern "C" void kernel_launch(void* const* d_in, const int* in_sizes, int n_in,
                              void* d_out, int out_size) {
    const float* x         = (const float*)d_in[0];
    const float* in_proj_w = (const float*)d_in[1];
    const float* conv_w    = (const float*)d_in[2];
    const float* conv_b    = (const float*)d_in[3];
    const float* x_proj_w  = (const float*)d_in[4];
    const float* dt_proj_w = (const float*)d_in[5];
    const float* dt_proj_b = (const float*)d_in[6];
    const float* A_log     = (const float*)d_in[7];
    const float* Dp        = (const float*)d_in[8];
    const float* out_proj_w= (const float*)d_in[9];
    const float* ln_g      = (const float*)d_in[10];
    const float* ln_b      = (const float*)d_in[11];
    float* out = (float*)d_out;

    float *p_xz, *p_uc, *p_dbc, *p_delta, *p_yz;
    cudaGetSymbolAddress((void**)&p_xz,    g_xz);
    cudaGetSymbolAddress((void**)&p_uc,    g_uc);
    cudaGetSymbolAddress((void**)&p_dbc,   g_dbc);
    cudaGetSymbolAddress((void**)&p_delta, g_delta);
    cudaGetSymbolAddress((void**)&p_yz,    g_yz);
    __half *pA1, *pB1, *pAdt, *pBdt, *pAy, *pBo;
    cudaGetSymbolAddress((void**)&pA1,  gA1);
    cudaGetSymbolAddress((void**)&pB1,  gB1);
    cudaGetSymbolAddress((void**)&pAdt, gAdt);
    cudaGetSymbolAddress((void**)&pBdt, gBdt);
    cudaGetSymbolAddress((void**)&pAy,  gAy);
    cudaGetSymbolAddress((void**)&pBo,  gBo);

    // 0. zero x_proj accumulator
    zero_kernel<<<(M_ROWS * XPROJ_N / 4 + 255) / 256, 256>>>(p_dbc, M_ROWS * XPROJ_N / 4);

    // 1. weight conversions (transpose + fp16 [hi|hi])
    wexpT<<<dim3((2*DIN)/32, DM/32),   256>>>(in_proj_w,  pB1, DM,  2*DIN);
    wexpT<<<dim3(DIN/32,     DTR/32),  256>>>(dt_proj_w,  pBdt, DTR, DIN);
    wexpT<<<dim3(DM/32,      DIN/32),  256>>>(out_proj_w, pBo, DIN, DM);

    // 2. layernorm + fp16 [hi|lo] expand
    ln_expand<<<M_ROWS, 256>>>(x, ln_g, ln_b);

    // 3. xz = xn @ in_proj_w  (fp16 2-term split: K' = 2048)
    gemm_mma<0><<<dim3((2*DIN)/128, M_ROWS/128), 256>>>(
        pA1, pB1, 2*DM, p_xz, 2*DIN, nullptr, 0);

    // 4. uc = silu(conv(u))
    conv_silu_kernel<<<(M_ROWS * DIN + 255) / 256, 256>>>(conv_w, conv_b);

    // 5. dbc += uc @ x_proj_w (fp32 split-K)
    {
        dim3 grid((XPROJ_N + 63) / 64, M_ROWS / 64, 8);
        gemm64_splitk<<<grid, 256>>>(p_uc, DIN, x_proj_w, XPROJ_N,
                                     p_dbc, XPROJ_N, XPROJ_N, DIN / 8);
    }

    // 6. expand dt slice; delta = softplus(dt @ dt_proj_w + b)  (K' = 128)
    aexp<<<(M_ROWS * (DTR/4) + 255) / 256, 256>>>(p_dbc, XPROJ_N, pAdt, DTR, M_ROWS);
    gemm_mma<1><<<dim3(DIN/128, M_ROWS/128), 256>>>(
        pAdt, pBdt, 2*DTR, p_delta, DIN, dt_proj_b, 0);

    // 7. selective scan + gate
    scan_kernel<<<(B_SZ * DIN / 2) / 4, 128>>>(A_log, Dp);

    // 8. expand yz; out = yz @ out_proj_w + x  (K' = 4096)
    aexp<<<(M_ROWS * (DIN/4) + 255) / 256, 256>>>(p_yz, DIN, pAy, DIN, M_ROWS);
    gemm_mma<2><<<dim3(DM/128, M_ROWS/128), 256>>>(
        pAy, pBo, 2*DIN, out, DM, x, DM);
}